// round 1
// baseline (speedup 1.0000x reference)
#include <cuda_runtime.h>
#include <cuda_bf16.h>
#include <cstdint>

// Problem constants
#define B_SZ  512
#define ZI    16
#define T_SZ  8
#define D     128
#define MROWS (B_SZ * ZI)   // 8192 img rows
#define NROWS (B_SZ * T_SZ) // 4096 text rows

// GEMM tiling
#define BM    128           // img rows per block (8 bi groups)
#define BN    64            // text rows per block (8 ct groups)
#define LDA   136           // padded bf16 row stride in smem (conflict-free)
#define GEMM_THREADS 256

// grid: 64 x-blocks over N, 64 y-blocks over M
#define NBX 64
#define NBY 64

// -------- device scratch (no allocations allowed) --------
__device__ uint4 g_imgn4[MROWS * D / 8];    // normalized img, bf16, 2 MB
__device__ uint4 g_textn4[NROWS * D / 8];   // normalized text, bf16, 1 MB
__device__ float g_part_i2t[NBX * B_SZ];    // [bx][bi] partial sums of exp
__device__ float g_part_t2i[NBY * NROWS];   // [by][textcol] partial sums of exp
__device__ float g_mdiag[B_SZ * T_SZ];      // M[bi,bi,t]
__device__ float g_logdent[NROWS];          // log den_t2i per text col

// ============================================================
// Kernel 1: L2 normalize rows of 128 f32 -> bf16
// one warp per row
// ============================================================
__global__ void normalize_kernel(const float* __restrict__ src, int which) {
    int gw   = (blockIdx.x * blockDim.x + threadIdx.x) >> 5;  // global row
    int lane = threadIdx.x & 31;
    const float4 v = reinterpret_cast<const float4*>(src)[gw * 32 + lane];
    float ss = v.x * v.x + v.y * v.y + v.z * v.z + v.w * v.w;
#pragma unroll
    for (int s = 16; s > 0; s >>= 1) ss += __shfl_xor_sync(0xffffffffu, ss, s);
    float inv = 1.0f / fmaxf(sqrtf(ss), 1e-12f);
    __nv_bfloat162* dst = reinterpret_cast<__nv_bfloat162*>(which ? g_textn4 : g_imgn4);
    dst[gw * 64 + lane * 2]     = __floats2bfloat162_rn(v.x * inv, v.y * inv);
    dst[gw * 64 + lane * 2 + 1] = __floats2bfloat162_rn(v.z * inv, v.w * inv);
}

// ============================================================
// Kernel 2: fused GEMM + max_i + exp + partial reductions
// block: 256 threads (8 warps). Warp w owns img rows w*16..w*16+15
// (exactly one bi group) x all 64 text cols of the block.
// ============================================================
extern __shared__ char smem_raw[];

__global__ void __launch_bounds__(GEMM_THREADS)
gemm_kernel() {
    __nv_bfloat16* As = reinterpret_cast<__nv_bfloat16*>(smem_raw);          // [128][136]
    __nv_bfloat16* Bs = As + BM * LDA;                                        // [64][136]
    float* ebuf = reinterpret_cast<float*>(smem_raw + (BM + BN) * LDA * 2);   // [8][64]

    const int bx = blockIdx.x, by = blockIdx.y;
    const int tid = threadIdx.x;
    const int w = tid >> 5, lane = tid & 31;

    // ---- load A tile (128x128 bf16) and B tile (64x128 bf16) into padded smem ----
    {
        const uint4* gA = g_imgn4 + (size_t)by * BM * (D / 8);
#pragma unroll
        for (int i = 0; i < 8; i++) {
            int idx = tid + i * GEMM_THREADS;          // 0..2047
            int r = idx >> 4, c = idx & 15;
            *reinterpret_cast<uint4*>(As + r * LDA + c * 8) = gA[idx];
        }
        const uint4* gB = g_textn4 + (size_t)bx * BN * (D / 8);
#pragma unroll
        for (int i = 0; i < 4; i++) {
            int idx = tid + i * GEMM_THREADS;          // 0..1023
            int r = idx >> 4, c = idx & 15;
            *reinterpret_cast<uint4*>(Bs + r * LDA + c * 8) = gB[idx];
        }
    }
    __syncthreads();

    // ---- mainloop: 8 k-steps of m16n8k16, 8 n-tiles per warp ----
    float acc[8][4];
#pragma unroll
    for (int nt = 0; nt < 8; nt++)
#pragma unroll
        for (int j = 0; j < 4; j++) acc[nt][j] = 0.0f;

    const int rgrp = lane >> 2;        // 0..7
    const int kq   = (lane & 3) * 2;   // 0,2,4,6
    const int arow = w * 16 + rgrp;

#pragma unroll
    for (int ks = 0; ks < 8; ks++) {
        const int k0 = ks * 16;
        uint32_t a0 = *reinterpret_cast<const uint32_t*>(As + arow * LDA + k0 + kq);
        uint32_t a1 = *reinterpret_cast<const uint32_t*>(As + (arow + 8) * LDA + k0 + kq);
        uint32_t a2 = *reinterpret_cast<const uint32_t*>(As + arow * LDA + k0 + kq + 8);
        uint32_t a3 = *reinterpret_cast<const uint32_t*>(As + (arow + 8) * LDA + k0 + kq + 8);
#pragma unroll
        for (int nt = 0; nt < 8; nt++) {
            const int brow = nt * 8 + rgrp;
            uint32_t b0 = *reinterpret_cast<const uint32_t*>(Bs + brow * LDA + k0 + kq);
            uint32_t b1 = *reinterpret_cast<const uint32_t*>(Bs + brow * LDA + k0 + kq + 8);
            asm volatile(
                "mma.sync.aligned.m16n8k16.row.col.f32.bf16.bf16.f32 "
                "{%0,%1,%2,%3}, {%4,%5,%6,%7}, {%8,%9}, {%0,%1,%2,%3};\n"
                : "+f"(acc[nt][0]), "+f"(acc[nt][1]), "+f"(acc[nt][2]), "+f"(acc[nt][3])
                : "r"(a0), "r"(a1), "r"(a2), "r"(a3), "r"(b0), "r"(b1));
        }
    }

    // ---- epilogue: max over the 16 img rows (=over i), exp, partial sums ----
    const int bi = by * 8 + w;
    float localsum = 0.0f;
    float M0s[8], M1s[8], e0s[8], e1s[8];

#pragma unroll
    for (int nt = 0; nt < 8; nt++) {
        // in-thread: rows rgrp and rgrp+8 share a column
        float m0 = fmaxf(acc[nt][0], acc[nt][2]);   // col nt*8 + 2*(lane%4)
        float m1 = fmaxf(acc[nt][1], acc[nt][3]);   // col nt*8 + 2*(lane%4)+1
        // reduce across the 8 row-groups (lane bits 2..4)
#pragma unroll
        for (int s = 4; s < 32; s <<= 1) {
            m0 = fmaxf(m0, __shfl_xor_sync(0xffffffffu, m0, s));
            m1 = fmaxf(m1, __shfl_xor_sync(0xffffffffu, m1, s));
        }
        float e0 = expf(m0), e1 = expf(m1);
        localsum += e0 + e1;
        M0s[nt] = m0; M1s[nt] = m1; e0s[nt] = e0; e1s[nt] = e1;
    }
    // sum over the 4 column classes (lane bits 0..1); rows duplicated so valid everywhere
    localsum += __shfl_xor_sync(0xffffffffu, localsum, 1);
    localsum += __shfl_xor_sync(0xffffffffu, localsum, 2);
    if (lane == 0) g_part_i2t[bx * B_SZ + bi] = localsum;    // unique writer

    if (lane < 4) {  // writer lanes: row-group 0, classes 0..3
#pragma unroll
        for (int nt = 0; nt < 8; nt++) {
            int c0 = nt * 8 + lane * 2;
            ebuf[w * 64 + c0]     = e0s[nt];
            ebuf[w * 64 + c0 + 1] = e1s[nt];
            int gc0 = bx * 64 + c0;
            if ((gc0 >> 3) == bi) g_mdiag[bi * 8 + (gc0 & 7)] = M0s[nt];
            int gc1 = gc0 + 1;
            if ((gc1 >> 3) == bi) g_mdiag[bi * 8 + (gc1 & 7)] = M1s[nt];
        }
    }
    __syncthreads();
    if (tid < 64) {  // per-column sum over the block's 8 bi values
        float s = 0.0f;
#pragma unroll
        for (int ww = 0; ww < 8; ww++) s += ebuf[ww * 64 + tid];
        g_part_t2i[by * NROWS + bx * 64 + tid] = s;          // unique writer
    }
}

// ============================================================
// Kernel 3: reduce den_t2i over the 64 by-blocks, take log
// ============================================================
__global__ void reduce_t2i_kernel() {
    int tc = blockIdx.x * blockDim.x + threadIdx.x;  // 0..4095
    float s = 0.0f;
#pragma unroll 8
    for (int byy = 0; byy < NBY; byy++) s += g_part_t2i[byy * NROWS + tc];
    g_logdent[tc] = logf(s);
}

// ============================================================
// Kernel 4: assemble the loss
// loss = sum_bi [ log den_i2t[bi] + sum_t log den_t2i[bi,t] - (9/8) sum_t Mdiag[bi,t] ]
// ============================================================
__global__ void finalize_kernel(float* __restrict__ out) {
    __shared__ float red[B_SZ];
    int bi = threadIdx.x;  // 512 threads
    float den_i = 0.0f;
#pragma unroll 8
    for (int bxx = 0; bxx < NBX; bxx++) den_i += g_part_i2t[bxx * B_SZ + bi];
    float contrib = logf(den_i);
#pragma unroll
    for (int t = 0; t < T_SZ; t++) {
        int tc = bi * 8 + t;
        contrib += g_logdent[tc] - 1.125f * g_mdiag[tc];
    }
    red[bi] = contrib;
    __syncthreads();
#pragma unroll
    for (int s = 256; s > 0; s >>= 1) {
        if (bi < s) red[bi] += red[bi + s];
        __syncthreads();
    }
    if (bi == 0) out[0] = red[0];
}

// ============================================================
extern "C" void kernel_launch(void* const* d_in, const int* in_sizes, int n_in,
                              void* d_out, int out_size) {
    const float* img  = (const float*)d_in[0];   // (512,16,128) f32
    const float* text = (const float*)d_in[1];   // (512,8,128) f32
    float* out = (float*)d_out;

    const int SMEM_BYTES = (BM + BN) * LDA * 2 + 8 * 64 * 4;  // 54272
    cudaFuncSetAttribute(gemm_kernel, cudaFuncAttributeMaxDynamicSharedMemorySize, SMEM_BYTES);

    normalize_kernel<<<MROWS * 32 / 256, 256>>>(img, 0);
    normalize_kernel<<<NROWS * 32 / 256, 256>>>(text, 1);
    gemm_kernel<<<dim3(NBX, NBY), GEMM_THREADS, SMEM_BYTES>>>();
    reduce_t2i_kernel<<<NROWS / 256, 256>>>();
    finalize_kernel<<<1, B_SZ>>>(out);
}

// round 2
// speedup vs baseline: 1.2698x; 1.2698x over previous
#include <cuda_runtime.h>
#include <cuda_bf16.h>
#include <cstdint>

// Problem constants
#define B_SZ  512
#define ZI    16
#define T_SZ  8
#define D     128
#define MROWS (B_SZ * ZI)   // 8192 img rows
#define NROWS (B_SZ * T_SZ) // 4096 text rows

// GEMM tiling: block computes 128x128, warp computes 32x64
#define BM    128
#define BN    128
#define LDA   136           // padded bf16 row stride (272B -> conflict-free ldmatrix)
#define GEMM_THREADS 256
#define NBX   (NROWS / BN)  // 32
#define NBY   (MROWS / BM)  // 64

// -------- device scratch (no allocations allowed) --------
__device__ uint4 g_imgn4[MROWS * D / 8];     // normalized img, bf16, 2 MB
__device__ uint4 g_textn4[NROWS * D / 8];    // normalized text, bf16, 1 MB
__device__ float g_part_i2t[B_SZ * 64];      // [bi][bx*2+wc] partial exp-sums
__device__ float g_part_t2i[NROWS * NBY];    // [col][by] partial exp-sums (transposed!)
__device__ float g_mdiag[B_SZ * T_SZ];       // M[bi,bi,t]
__device__ float g_slt[B_SZ];                // sum_t log den_t2i[bi,t]

// ============================================================
// Kernel 1: L2 normalize rows of 128 f32 -> bf16 (both tensors)
// one warp per row
// ============================================================
__global__ void normalize_kernel(const float* __restrict__ img,
                                 const float* __restrict__ text) {
    int row  = (blockIdx.x * blockDim.x + threadIdx.x) >> 5;
    int lane = threadIdx.x & 31;
    const float* src;
    __nv_bfloat162* dst;
    int lrow;
    if (row < MROWS) { src = img;  lrow = row;         dst = reinterpret_cast<__nv_bfloat162*>(g_imgn4); }
    else             { src = text; lrow = row - MROWS; dst = reinterpret_cast<__nv_bfloat162*>(g_textn4); }
    const float4 v = reinterpret_cast<const float4*>(src)[lrow * 32 + lane];
    float ss = v.x * v.x + v.y * v.y + v.z * v.z + v.w * v.w;
#pragma unroll
    for (int s = 16; s > 0; s >>= 1) ss += __shfl_xor_sync(0xffffffffu, ss, s);
    float inv = rsqrtf(fmaxf(ss, 1e-24f));
    dst[lrow * 64 + lane * 2]     = __floats2bfloat162_rn(v.x * inv, v.y * inv);
    dst[lrow * 64 + lane * 2 + 1] = __floats2bfloat162_rn(v.z * inv, v.w * inv);
}

// ============================================================
// Kernel 2: fused GEMM + max_i + exp + partial reductions
// 256 threads = 8 warps; warp w: rows (w>>1)*32..+31, cols (w&1)*64..+63
// ============================================================
extern __shared__ char smem_raw[];

__device__ __forceinline__ void mma16816(float* c, const uint32_t* a, uint32_t b0, uint32_t b1) {
    asm volatile(
        "mma.sync.aligned.m16n8k16.row.col.f32.bf16.bf16.f32 "
        "{%0,%1,%2,%3}, {%4,%5,%6,%7}, {%8,%9}, {%0,%1,%2,%3};\n"
        : "+f"(c[0]), "+f"(c[1]), "+f"(c[2]), "+f"(c[3])
        : "r"(a[0]), "r"(a[1]), "r"(a[2]), "r"(a[3]), "r"(b0), "r"(b1));
}

__global__ void __launch_bounds__(GEMM_THREADS, 2)
gemm_kernel() {
    __nv_bfloat16* As = reinterpret_cast<__nv_bfloat16*>(smem_raw);          // [128][136]
    __nv_bfloat16* Bs = As + BM * LDA;                                        // [128][136]
    float* ebuf = reinterpret_cast<float*>(smem_raw + (BM + BN) * LDA * 2);   // [4][128]

    const int bx = blockIdx.x, by = blockIdx.y;
    const int tid = threadIdx.x;
    const int w = tid >> 5, lane = tid & 31;
    const int wr = w >> 1, wc = w & 1;

    // ---- load tiles (each 128x128 bf16 = 32KB) ----
    {
        const uint4* gA = g_imgn4 + (size_t)by * BM * (D / 8);
        const uint4* gB = g_textn4 + (size_t)bx * BN * (D / 8);
#pragma unroll
        for (int i = 0; i < 8; i++) {
            int idx = tid + i * GEMM_THREADS;          // 0..2047
            int r = idx >> 4, c = idx & 15;
            *reinterpret_cast<uint4*>(As + r * LDA + c * 8) = gA[idx];
            *reinterpret_cast<uint4*>(Bs + r * LDA + c * 8) = gB[idx];
        }
    }
    __syncthreads();

    // ---- ldmatrix base addresses ----
    uint32_t sA = (uint32_t)__cvta_generic_to_shared(As);
    uint32_t sB = (uint32_t)__cvta_generic_to_shared(Bs);
    uint32_t aAddr[2], bAddr[4];
#pragma unroll
    for (int mt = 0; mt < 2; mt++)
        aAddr[mt] = sA + (((wr * 32 + mt * 16 + (lane & 15)) * LDA) + ((lane & 16) ? 8 : 0)) * 2;
#pragma unroll
    for (int p = 0; p < 4; p++)
        bAddr[p] = sB + (((wc * 64 + p * 16 + (lane & 7) + ((lane & 16) ? 8 : 0)) * LDA) + ((lane & 8) ? 8 : 0)) * 2;

    float acc[2][8][4];
#pragma unroll
    for (int mt = 0; mt < 2; mt++)
#pragma unroll
        for (int nt = 0; nt < 8; nt++)
#pragma unroll
            for (int j = 0; j < 4; j++) acc[mt][nt][j] = 0.0f;

    // ---- mainloop: 8 k-steps ----
#pragma unroll
    for (int ks = 0; ks < 8; ks++) {
        uint32_t a[2][4];
#pragma unroll
        for (int mt = 0; mt < 2; mt++)
            asm volatile("ldmatrix.sync.aligned.m8n8.x4.shared.b16 {%0,%1,%2,%3}, [%4];\n"
                         : "=r"(a[mt][0]), "=r"(a[mt][1]), "=r"(a[mt][2]), "=r"(a[mt][3])
                         : "r"(aAddr[mt] + ks * 32));
        uint32_t b[4][4];
#pragma unroll
        for (int p = 0; p < 4; p++)
            asm volatile("ldmatrix.sync.aligned.m8n8.x4.shared.b16 {%0,%1,%2,%3}, [%4];\n"
                         : "=r"(b[p][0]), "=r"(b[p][1]), "=r"(b[p][2]), "=r"(b[p][3])
                         : "r"(bAddr[p] + ks * 32));
#pragma unroll
        for (int mt = 0; mt < 2; mt++)
#pragma unroll
            for (int nt = 0; nt < 8; nt++)
                mma16816(acc[mt][nt], a[mt], b[nt >> 1][(nt & 1) * 2], b[nt >> 1][(nt & 1) * 2 + 1]);
    }

    // ---- epilogue ----
    // lane owns (after redistribution) cols c0=2*lane, c0+1 of the warp's 64
    float cs0 = 0.0f, cs1 = 0.0f;
#pragma unroll
    for (int mt = 0; mt < 2; mt++) {
        const int bi = by * 8 + wr * 2 + mt;
        float M0s[8], M1s[8];
#pragma unroll
        for (int nt = 0; nt < 8; nt++) {
            float m0 = fmaxf(acc[mt][nt][0], acc[mt][nt][2]);
            float m1 = fmaxf(acc[mt][nt][1], acc[mt][nt][3]);
#pragma unroll
            for (int s = 4; s < 32; s <<= 1) {
                m0 = fmaxf(m0, __shfl_xor_sync(0xffffffffu, m0, s));
                m1 = fmaxf(m1, __shfl_xor_sync(0xffffffffu, m1, s));
            }
            M0s[nt] = m0; M1s[nt] = m1;
        }
        // redistribute: lane L takes (nt = L>>2, class = L&3) -> cols 2L, 2L+1
        float m0v = 0.0f, m1v = 0.0f;
#pragma unroll
        for (int nt = 0; nt < 8; nt++) {
            float t0 = __shfl_sync(0xffffffffu, M0s[nt], lane & 3);
            float t1 = __shfl_sync(0xffffffffu, M1s[nt], lane & 3);
            if ((lane >> 2) == nt) { m0v = t0; m1v = t1; }
        }
        float e0 = __expf(m0v), e1 = __expf(m1v);
        cs0 += e0; cs1 += e1;
        // per-bi partial sum over this warp's 64 cols (each lane 2 distinct cols)
        float ls = e0 + e1;
#pragma unroll
        for (int s = 1; s < 32; s <<= 1) ls += __shfl_xor_sync(0xffffffffu, ls, s);
        if (lane == 0) g_part_i2t[bi * 64 + bx * 2 + wc] = ls;   // unique writer
        // diagonal capture
        int gc = bx * 128 + wc * 64 + 2 * lane;
        if ((gc >> 3) == bi) {
            g_mdiag[bi * 8 + (gc & 7)]       = m0v;
            g_mdiag[bi * 8 + ((gc + 1) & 7)] = m1v;
        }
    }
    // per-column partial over this warp's 32 rows (2 bi groups)
    *reinterpret_cast<float2*>(&ebuf[wr * 128 + wc * 64 + 2 * lane]) = make_float2(cs0, cs1);
    __syncthreads();
    if (tid < 128) {
        float s = ebuf[tid] + ebuf[128 + tid] + ebuf[256 + tid] + ebuf[384 + tid];
        g_part_t2i[(bx * 128 + tid) * NBY + by] = s;             // unique writer
    }
}

// ============================================================
// Kernel 3: per-bi sum of log(den_t2i). warp per bi (512 warps).
// ============================================================
__global__ void reduce_bi_kernel() {
    int w = threadIdx.x >> 5, lane = threadIdx.x & 31;
    int bi = blockIdx.x * 8 + w;
    int t = lane >> 2, q = lane & 3;
    const float4* p = reinterpret_cast<const float4*>(&g_part_t2i[(bi * 8 + t) * NBY + q * 16]);
    float4 x0 = p[0], x1 = p[1], x2 = p[2], x3 = p[3];
    float s = ((x0.x + x0.y) + (x0.z + x0.w)) + ((x1.x + x1.y) + (x1.z + x1.w))
            + ((x2.x + x2.y) + (x2.z + x2.w)) + ((x3.x + x3.y) + (x3.z + x3.w));
    s += __shfl_xor_sync(0xffffffffu, s, 1);
    s += __shfl_xor_sync(0xffffffffu, s, 2);
    float v = (q == 0) ? __logf(s) : 0.0f;
#pragma unroll
    for (int sh = 1; sh < 32; sh <<= 1) v += __shfl_xor_sync(0xffffffffu, v, sh);
    if (lane == 0) g_slt[bi] = v;
}

// ============================================================
// Kernel 4: assemble the loss
// loss = sum_bi [ log den_i2t[bi] + slt[bi] - (9/8) sum_t Mdiag[bi,t] ]
// ============================================================
__global__ void finalize_kernel(float* __restrict__ out) {
    __shared__ float red[B_SZ];
    int bi = threadIdx.x;  // 512 threads
    const float4* p = reinterpret_cast<const float4*>(&g_part_i2t[bi * 64]);
    float den = 0.0f;
#pragma unroll
    for (int i = 0; i < 16; i++) { float4 v = p[i]; den += (v.x + v.y) + (v.z + v.w); }
    const float4* md = reinterpret_cast<const float4*>(&g_mdiag[bi * 8]);
    float4 m0 = md[0], m1 = md[1];
    float ms = ((m0.x + m0.y) + (m0.z + m0.w)) + ((m1.x + m1.y) + (m1.z + m1.w));
    red[bi] = __logf(den) + g_slt[bi] - 1.125f * ms;
    __syncthreads();
#pragma unroll
    for (int s = 256; s > 0; s >>= 1) {
        if (bi < s) red[bi] += red[bi + s];
        __syncthreads();
    }
    if (bi == 0) out[0] = red[0];
}

// ============================================================
extern "C" void kernel_launch(void* const* d_in, const int* in_sizes, int n_in,
                              void* d_out, int out_size) {
    const float* img  = (const float*)d_in[0];   // (512,16,128) f32
    const float* text = (const float*)d_in[1];   // (512,8,128) f32
    float* out = (float*)d_out;

    const int SMEM_BYTES = (BM + BN) * LDA * 2 + 4 * 128 * 4;  // 71680
    cudaFuncSetAttribute(gemm_kernel, cudaFuncAttributeMaxDynamicSharedMemorySize, SMEM_BYTES);

    normalize_kernel<<<(MROWS + NROWS) * 32 / 256, 256>>>(img, text);
    gemm_kernel<<<dim3(NBX, NBY), GEMM_THREADS, SMEM_BYTES>>>();
    reduce_bi_kernel<<<B_SZ / 8, 256>>>();
    finalize_kernel<<<1, B_SZ>>>(out);
}

// round 4
// speedup vs baseline: 1.5583x; 1.2271x over previous
#include <cuda_runtime.h>
#include <cuda_bf16.h>
#include <cstdint>

// Problem constants
#define B_SZ  512
#define ZI    16
#define T_SZ  8
#define D     128
#define MROWS (B_SZ * ZI)   // 8192 img rows
#define NROWS (B_SZ * T_SZ) // 4096 text rows

// GEMM tiling: block computes 128x128, warp computes 32x64, fp8 k-step 32
#define BM    128
#define BN    128
#define LDS8  144           // padded fp8 row stride in bytes (conflict-free)
#define GEMM_THREADS 256
#define NBX   (NROWS / BN)  // 32
#define NBY   (MROWS / BM)  // 64

// dynamic smem layout (bytes)
#define SMEM_A     0
#define SMEM_B     (BM * LDS8)              // 18432
#define SMEM_EBUF  (SMEM_B + BN * LDS8)     // 36864
#define SMEM_TOTAL (SMEM_EBUF + 8 * 128 * 4)

// -------- device scratch (no allocations allowed) --------
__device__ uint4 g_imgn8[MROWS * D / 16];    // normalized img, e4m3, 1 MB
__device__ uint4 g_textn8[NROWS * D / 16];   // normalized text, e4m3, 0.5 MB
__device__ float g_part_i2t[B_SZ * 64];      // [bi][bx*2+wc] partial exp-sums
__device__ float g_part_t2i[NROWS * NBY];    // [col][by] partial exp-sums (transposed)
__device__ float g_mdiag[B_SZ * T_SZ];       // M[bi,bi,t]
__device__ float g_blockpart[NBY];           // per-block loss partials

// ============================================================
// Kernel 1: L2 normalize rows of 128 f32 -> e4m3 (both tensors)
// one warp per row; lane packs 4 fp8 into one uint32
// ============================================================
__global__ void normalize_kernel(const float* __restrict__ img,
                                 const float* __restrict__ text) {
    int row  = (blockIdx.x * blockDim.x + threadIdx.x) >> 5;
    int lane = threadIdx.x & 31;
    const float* src;
    uint32_t* dst;
    int lrow;
    if (row < MROWS) { src = img;  lrow = row;         dst = reinterpret_cast<uint32_t*>(g_imgn8); }
    else             { src = text; lrow = row - MROWS; dst = reinterpret_cast<uint32_t*>(g_textn8); }
    const float4 v = reinterpret_cast<const float4*>(src)[lrow * 32 + lane];
    float ss = v.x * v.x + v.y * v.y + v.z * v.z + v.w * v.w;
#pragma unroll
    for (int s = 16; s > 0; s >>= 1) ss += __shfl_xor_sync(0xffffffffu, ss, s);
    float inv = rsqrtf(fmaxf(ss, 1e-24f));
    uint32_t pack;
    asm("{ .reg .b16 lo, hi;\n\t"
        "cvt.rn.satfinite.e4m3x2.f32 lo, %2, %1;\n\t"
        "cvt.rn.satfinite.e4m3x2.f32 hi, %4, %3;\n\t"
        "mov.b32 %0, {lo, hi}; }"
        : "=r"(pack)
        : "f"(v.x * inv), "f"(v.y * inv), "f"(v.z * inv), "f"(v.w * inv));
    dst[lrow * 32 + lane] = pack;
}

// ============================================================
// Kernel 2: fused fp8 GEMM + max_i + exp + partial reductions
// 256 threads = 8 warps; warp w: rows (w>>1)*32..+31, cols (w&1)*64..+63
// ============================================================
extern __shared__ char smem_raw[];

__device__ __forceinline__ void mma_fp8(float* c, const uint32_t* a, uint32_t b0, uint32_t b1) {
    asm volatile(
        "mma.sync.aligned.m16n8k32.row.col.f32.e4m3.e4m3.f32 "
        "{%0,%1,%2,%3}, {%4,%5,%6,%7}, {%8,%9}, {%0,%1,%2,%3};\n"
        : "+f"(c[0]), "+f"(c[1]), "+f"(c[2]), "+f"(c[3])
        : "r"(a[0]), "r"(a[1]), "r"(a[2]), "r"(a[3]), "r"(b0), "r"(b1));
}

__global__ void __launch_bounds__(GEMM_THREADS, 2)
gemm_kernel() {
    char* As = smem_raw + SMEM_A;    // [128][144] fp8
    char* Bs = smem_raw + SMEM_B;    // [128][144] fp8
    float* ebuf = reinterpret_cast<float*>(smem_raw + SMEM_EBUF);  // [8][128]

    const int bx = blockIdx.x, by = blockIdx.y;
    const int tid = threadIdx.x;
    const int w = tid >> 5, lane = tid & 31;
    const int wr = w >> 1, wc = w & 1;

    // ---- load tiles (each 128x128 fp8 = 16KB) into padded smem ----
    {
        const uint4* gA = g_imgn8 + (size_t)by * BM * (D / 16);
        const uint4* gB = g_textn8 + (size_t)bx * BN * (D / 16);
#pragma unroll
        for (int i = 0; i < 4; i++) {
            int idx = tid + i * GEMM_THREADS;          // 0..1023
            int r = idx >> 3, c = idx & 7;
            *reinterpret_cast<uint4*>(As + r * LDS8 + c * 16) = gA[idx];
            *reinterpret_cast<uint4*>(Bs + r * LDS8 + c * 16) = gB[idx];
        }
    }
    __syncthreads();

    // ---- ldmatrix base addresses (fp8: k-half = 16 bytes) ----
    uint32_t sA = (uint32_t)__cvta_generic_to_shared(As);
    uint32_t sB = (uint32_t)__cvta_generic_to_shared(Bs);
    uint32_t aAddr[2], bAddr[4];
#pragma unroll
    for (int mt = 0; mt < 2; mt++)
        aAddr[mt] = sA + (wr * 32 + mt * 16 + (lane & 15)) * LDS8 + ((lane & 16) ? 16 : 0);
#pragma unroll
    for (int p = 0; p < 4; p++)
        bAddr[p] = sB + (wc * 64 + p * 16 + (lane & 7) + ((lane & 16) ? 8 : 0)) * LDS8 + ((lane & 8) ? 16 : 0);

    float acc[2][8][4];
#pragma unroll
    for (int mt = 0; mt < 2; mt++)
#pragma unroll
        for (int nt = 0; nt < 8; nt++)
#pragma unroll
            for (int j = 0; j < 4; j++) acc[mt][nt][j] = 0.0f;

    // ---- mainloop: 4 k-steps of 32 ----
#pragma unroll
    for (int ks = 0; ks < 4; ks++) {
        uint32_t a[2][4];
#pragma unroll
        for (int mt = 0; mt < 2; mt++)
            asm volatile("ldmatrix.sync.aligned.m8n8.x4.shared.b16 {%0,%1,%2,%3}, [%4];\n"
                         : "=r"(a[mt][0]), "=r"(a[mt][1]), "=r"(a[mt][2]), "=r"(a[mt][3])
                         : "r"(aAddr[mt] + ks * 32));
        uint32_t b[4][4];
#pragma unroll
        for (int p = 0; p < 4; p++)
            asm volatile("ldmatrix.sync.aligned.m8n8.x4.shared.b16 {%0,%1,%2,%3}, [%4];\n"
                         : "=r"(b[p][0]), "=r"(b[p][1]), "=r"(b[p][2]), "=r"(b[p][3])
                         : "r"(bAddr[p] + ks * 32));
#pragma unroll
        for (int mt = 0; mt < 2; mt++)
#pragma unroll
            for (int nt = 0; nt < 8; nt++)
                mma_fp8(acc[mt][nt], a[mt], b[nt >> 1][(nt & 1) * 2], b[nt >> 1][(nt & 1) * 2 + 1]);
    }

    // ---- epilogue (identical layout to bf16 m16n8 C fragment) ----
    float cs0 = 0.0f, cs1 = 0.0f;
#pragma unroll
    for (int mt = 0; mt < 2; mt++) {
        const int bi = by * 8 + wr * 2 + mt;
        float M0s[8], M1s[8];
#pragma unroll
        for (int nt = 0; nt < 8; nt++) {
            float m0 = fmaxf(acc[mt][nt][0], acc[mt][nt][2]);
            float m1 = fmaxf(acc[mt][nt][1], acc[mt][nt][3]);
#pragma unroll
            for (int s = 4; s < 32; s <<= 1) {
                m0 = fmaxf(m0, __shfl_xor_sync(0xffffffffu, m0, s));
                m1 = fmaxf(m1, __shfl_xor_sync(0xffffffffu, m1, s));
            }
            M0s[nt] = m0; M1s[nt] = m1;
        }
        // redistribute: lane L takes (nt = L>>2, class = L&3) -> cols 2L, 2L+1
        float m0v = 0.0f, m1v = 0.0f;
#pragma unroll
        for (int nt = 0; nt < 8; nt++) {
            float t0 = __shfl_sync(0xffffffffu, M0s[nt], lane & 3);
            float t1 = __shfl_sync(0xffffffffu, M1s[nt], lane & 3);
            if ((lane >> 2) == nt) { m0v = t0; m1v = t1; }
        }
        float e0 = __expf(m0v), e1 = __expf(m1v);
        cs0 += e0; cs1 += e1;
        // per-bi partial sum over this warp's 64 cols
        float ls = e0 + e1;
#pragma unroll
        for (int s = 1; s < 32; s <<= 1) ls += __shfl_xor_sync(0xffffffffu, ls, s);
        if (lane == 0) g_part_i2t[bi * 64 + bx * 2 + wc] = ls;   // unique writer
        // diagonal capture
        int gc = bx * 128 + wc * 64 + 2 * lane;
        if ((gc >> 3) == bi) {
            g_mdiag[bi * 8 + (gc & 7)]       = m0v;
            g_mdiag[bi * 8 + ((gc + 1) & 7)] = m1v;
        }
    }
    // per-column partial over this warp's 32 rows (2 bi groups) -> ebuf
    *reinterpret_cast<float2*>(&ebuf[wr * 128 + wc * 64 + 2 * lane]) = make_float2(cs0, cs1);
    __syncthreads();
    if (tid < 128) {
        float s = ebuf[tid] + ebuf[128 + tid] + ebuf[256 + tid] + ebuf[384 + tid];
        g_part_t2i[(bx * 128 + tid) * NBY + by] = s;             // unique writer
    }
}

// ============================================================
// Kernel 3: per-bi loss contribution. warp per bi, 8 warps/block.
// contrib = log(den_i2t) + sum_t log(den_t2i) - 1.125 * sum_t Mdiag
// ============================================================
__global__ void reduce_bi_kernel() {
    __shared__ float red[8];
    int w = threadIdx.x >> 5, lane = threadIdx.x & 31;
    int bi = blockIdx.x * 8 + w;
    // slt: sum over t of log den_t2i
    int t = lane >> 2, q = lane & 3;
    const float4* p = reinterpret_cast<const float4*>(&g_part_t2i[(bi * 8 + t) * NBY + q * 16]);
    float4 x0 = p[0], x1 = p[1], x2 = p[2], x3 = p[3];
    float s = ((x0.x + x0.y) + (x0.z + x0.w)) + ((x1.x + x1.y) + (x1.z + x1.w))
            + ((x2.x + x2.y) + (x2.z + x2.w)) + ((x3.x + x3.y) + (x3.z + x3.w));
    s += __shfl_xor_sync(0xffffffffu, s, 1);
    s += __shfl_xor_sync(0xffffffffu, s, 2);
    float v = (q == 0) ? __logf(s) : 0.0f;
    // den_i2t over 64 partials
    float2 di2 = reinterpret_cast<const float2*>(&g_part_i2t[bi * 64])[lane];
    float den = di2.x + di2.y;
    // mdiag (8 values)
    float md = (lane < 8) ? g_mdiag[bi * 8 + lane] : 0.0f;
#pragma unroll
    for (int sh = 1; sh < 32; sh <<= 1) {
        v   += __shfl_xor_sync(0xffffffffu, v, sh);
        den += __shfl_xor_sync(0xffffffffu, den, sh);
        md  += __shfl_xor_sync(0xffffffffu, md, sh);
    }
    if (lane == 0) red[w] = __logf(den) + v - 1.125f * md;
    __syncthreads();
    if (threadIdx.x == 0) {
        float c = 0.0f;
#pragma unroll
        for (int i = 0; i < 8; i++) c += red[i];
        g_blockpart[blockIdx.x] = c;
    }
}

// ============================================================
// Kernel 4: tiny final sum over 64 block partials
// ============================================================
__global__ void final_kernel(float* __restrict__ out) {
    int lane = threadIdx.x;
    float s = g_blockpart[lane] + g_blockpart[lane + 32];
#pragma unroll
    for (int sh = 16; sh > 0; sh >>= 1) s += __shfl_xor_sync(0xffffffffu, s, sh);
    if (lane == 0) out[0] = s;
}

// ============================================================
extern "C" void kernel_launch(void* const* d_in, const int* in_sizes, int n_in,
                              void* d_out, int out_size) {
    const float* img  = (const float*)d_in[0];   // (512,16,128) f32
    const float* text = (const float*)d_in[1];   // (512,8,128) f32
    float* out = (float*)d_out;

    cudaFuncSetAttribute(gemm_kernel, cudaFuncAttributeMaxDynamicSharedMemorySize, SMEM_TOTAL);

    normalize_kernel<<<(MROWS + NROWS) * 32 / 256, 256>>>(img, text);
    gemm_kernel<<<dim3(NBX, NBY), GEMM_THREADS, SMEM_TOTAL>>>();
    reduce_bi_kernel<<<B_SZ / 8, 256>>>();
    final_kernel<<<1, 32>>>(out);
}